// round 6
// baseline (speedup 1.0000x reference)
#include <cuda_runtime.h>
#include <math.h>

#define BB 512
#define TT 2048
#define CC 64

__device__ int   g_i0[TT];
__device__ float g_w0[TT];
__device__ float g_w1[TT];
__device__ float g_ca[BB];
__device__ float g_sa[BB];
__device__ float g_mask[CC];

// One-block prep with parallel scan.
__global__ void __launch_bounds__(512) prep_kernel(
    const float* __restrict__ scale_u,
    const float* __restrict__ warp_noise,
    const float* __restrict__ angle_u,
    const float* __restrict__ chmask_u)
{
    __shared__ float cum[TT];
    __shared__ float wsum[8];
    const int tid  = threadIdx.x;         // 512 threads
    const int lane = tid & 31;
    const int wid  = tid >> 5;
    const float k = 0.2f / (float)TT;     // TW_SIGMA / T

    float loc[8];
    float myTotal = 0.f, inc = 0.f;
    if (tid < 256) {
        float run = 0.f;
        #pragma unroll
        for (int i = 0; i < 8; i++) {
            run += warp_noise[tid * 8 + i] * k;
            loc[i] = run;
        }
        myTotal = run;
        inc = myTotal;
        #pragma unroll
        for (int d = 1; d < 32; d <<= 1) {
            float o = __shfl_up_sync(0xffffffffu, inc, d);
            if (lane >= d) inc += o;
        }
        if (lane == 31) wsum[wid] = inc;
    }
    __syncthreads();
    if (tid == 0) {
        float a = 0.f;
        #pragma unroll
        for (int j = 0; j < 8; j++) { float v = wsum[j]; wsum[j] = a; a += v; }
    }
    __syncthreads();
    if (tid < 256) {
        float excl = (inc - myTotal) + wsum[wid];
        #pragma unroll
        for (int i = 0; i < 8; i++) cum[tid * 8 + i] = excl + loc[i];
    }
    __syncthreads();

    const float c0    = cum[0];
    const float denom = (cum[TT - 1] - c0) + 1e-8f;
    const float scale = 0.9f + scale_u[0] * 0.2f;

    if (tid < 256) {
        #pragma unroll
        for (int i = 0; i < 8; i++) {
            int t = tid * 8 + i;
            float w  = (cum[t] - c0) / denom;
            float tw = (float)t / (float)(TT - 1) + 0.2f * w;
            tw = fminf(fmaxf(tw, 0.f), 1.f);
            float pos = tw * (float)(TT - 1);
            int i0 = (int)floorf(pos);
            i0 = min(max(i0, 0), TT - 2);
            float frac = pos - (float)i0;
            g_i0[t] = i0;
            g_w0[t] = scale * (1.f - frac);
            g_w1[t] = scale * frac;
        }
    }

    {   // per-batch rotation (512 threads == B)
        float ang = angle_u[tid] * 6.283185307179586f - 3.141592653589793f;
        g_ca[tid] = cosf(ang);
        g_sa[tid] = sinf(ang);
    }
    if (tid < CC) g_mask[tid] = (chmask_u[tid] > 0.1f) ? 1.f : 0.f;
}

__device__ __forceinline__ float4 lerp_row(float4 a0, float4 a1,
                                           float4 p0, float4 p1,
                                           float w0, float w1)
{
    const float J = 0.01f;
    float4 v;
    v.x = w0 * fmaf(J, p0.x, a0.x) + w1 * fmaf(J, p1.x, a1.x);
    v.y = w0 * fmaf(J, p0.y, a0.y) + w1 * fmaf(J, p1.y, a1.y);
    v.z = w0 * fmaf(J, p0.z, a0.z) + w1 * fmaf(J, p1.z, a1.z);
    v.w = w0 * fmaf(J, p0.w, a0.w) + w1 * fmaf(J, p1.w, a1.w);
    return v;
}

// Fused main pass: 16 contiguous threads per 64-channel row (fully coalesced
// float4 accesses). Each thread handles FOUR adjacent t-rows of one batch,
// as two load-groups of 8 LDG.128 so live registers stay moderate while
// ptxas hoists group-B loads into group-A's compute shadow.
__global__ void __launch_bounds__(256) aug_kernel(
    const float4* __restrict__ x,
    const float4* __restrict__ nz,
    float4* __restrict__ out)
{
    const int gid   = blockIdx.x * 256 + threadIdx.x;
    const int lane  = gid & 15;           // float4 index within row
    const int q     = gid >> 4;           // quad index
    const int row0  = q * 4;              // b*T + t0 (t0 multiple of 4)
    const int t0    = row0 & (TT - 1);
    const int b     = row0 >> 11;         // T = 2048 = 2^11

    const int   iA = g_i0[t0],     iB = g_i0[t0 + 1];
    const int   iC = g_i0[t0 + 2], iD = g_i0[t0 + 3];
    const float w0A = g_w0[t0],     w1A = g_w1[t0];
    const float w0B = g_w0[t0 + 1], w1B = g_w1[t0 + 1];
    const float w0C = g_w0[t0 + 2], w1C = g_w1[t0 + 2];
    const float w0D = g_w0[t0 + 3], w1D = g_w1[t0 + 3];

    const size_t bb = (size_t)b * TT * 16 + (size_t)lane;
    const size_t baA = bb + (size_t)iA * 16;
    const size_t baB = bb + (size_t)iB * 16;
    const size_t baC = bb + (size_t)iC * 16;
    const size_t baD = bb + (size_t)iD * 16;

    // ---- group A: rows t0, t0+1 (8 coalesced LDG.128) ----
    const float4 xA0 = __ldg(x  + baA);
    const float4 xA1 = __ldg(x  + baA + 16);
    const float4 xB0 = __ldg(x  + baB);
    const float4 xB1 = __ldg(x  + baB + 16);
    const float4 nA0 = __ldg(nz + baA);
    const float4 nA1 = __ldg(nz + baA + 16);
    const float4 nB0 = __ldg(nz + baB);
    const float4 nB1 = __ldg(nz + baB + 16);

    float4 vA = lerp_row(xA0, xA1, nA0, nA1, w0A, w1A);
    float4 vB = lerp_row(xB0, xB1, nB0, nB1, w0B, w1B);

    // ---- group B: rows t0+2, t0+3 (8 coalesced LDG.128) ----
    const float4 xC0 = __ldg(x  + baC);
    const float4 xC1 = __ldg(x  + baC + 16);
    const float4 xD0 = __ldg(x  + baD);
    const float4 xD1 = __ldg(x  + baD + 16);
    const float4 nC0 = __ldg(nz + baC);
    const float4 nC1 = __ldg(nz + baC + 16);
    const float4 nD0 = __ldg(nz + baD);
    const float4 nD1 = __ldg(nz + baD + 16);

    float4 vC = lerp_row(xC0, xC1, nC0, nC1, w0C, w1C);
    float4 vD = lerp_row(xD0, xD1, nD0, nD1, w0D, w1D);

    if (lane == 0) {  // channels 0,1 rotation (same batch for all 4 rows)
        const float ca = g_ca[b], sa = g_sa[b];
        float r0, r1;
        r0 = ca * vA.x - sa * vA.y; r1 = sa * vA.x + ca * vA.y; vA.x = r0; vA.y = r1;
        r0 = ca * vB.x - sa * vB.y; r1 = sa * vB.x + ca * vB.y; vB.x = r0; vB.y = r1;
        r0 = ca * vC.x - sa * vC.y; r1 = sa * vC.x + ca * vC.y; vC.x = r0; vC.y = r1;
        r0 = ca * vD.x - sa * vD.y; r1 = sa * vD.x + ca * vD.y; vD.x = r0; vD.y = r1;
    }

    const float4 m = reinterpret_cast<const float4*>(g_mask)[lane];
    vA.x *= m.x; vA.y *= m.y; vA.z *= m.z; vA.w *= m.w;
    vB.x *= m.x; vB.y *= m.y; vB.z *= m.z; vB.w *= m.w;
    vC.x *= m.x; vC.y *= m.y; vC.z *= m.z; vC.w *= m.w;
    vD.x *= m.x; vD.y *= m.y; vD.z *= m.z; vD.w *= m.w;

    const size_t ob = (size_t)row0 * 16 + (size_t)lane;
    __stcs(out + ob,      vA);
    __stcs(out + ob + 16, vB);
    __stcs(out + ob + 32, vC);
    __stcs(out + ob + 48, vD);
}

extern "C" void kernel_launch(void* const* d_in, const int* in_sizes, int n_in,
                              void* d_out, int out_size)
{
    const float* x        = (const float*)d_in[0];
    const float* noise    = (const float*)d_in[1];
    const float* scale_u  = (const float*)d_in[2];
    const float* warp_n   = (const float*)d_in[3];
    const float* angle_u  = (const float*)d_in[4];
    const float* chmask_u = (const float*)d_in[5];
    float* out = (float*)d_out;

    prep_kernel<<<1, 512>>>(scale_u, warp_n, angle_u, chmask_u);

    // B*T/4 quads * 16 threads each
    const int total_threads = BB * TT * 4;
    aug_kernel<<<total_threads / 256, 256>>>(
        (const float4*)x, (const float4*)noise, (float4*)out);
}